// round 10
// baseline (speedup 1.0000x reference)
#include <cuda_runtime.h>
#include <cuda_fp16.h>
#include <math.h>
#include <cstdint>

#define N_TOK 1024
#define TOPK  2
#define NEXP  16
#define HID   1024
#define DIM   2048
#define RNK   16
#define NKTOT (N_TOK*TOPK)
#define LSCALE 0.25f

// ---------------- scratch (static device globals; no allocation) ----------------
__device__ int   g_cnt[NEXP];
__device__ int   g_list[NEXP*NKTOT];
__device__ __align__(16) float  g_t[NKTOT*RNK];
__device__ __align__(16) float  g_t2[NKTOT*RNK];
__device__ __align__(16) __half g_act_h[(size_t)NKTOT*HID];
__device__ __align__(16) float  g_down[(size_t)NKTOT*DIM];

// ---------------- helpers ----------------
__device__ __forceinline__ uint32_t smem_u32(const void* p){
    uint32_t a;
    asm("{ .reg .u64 t; cvta.to.shared.u64 t, %1; cvt.u32.u64 %0, t; }":"=r"(a):"l"(p));
    return a;
}
__device__ __forceinline__ uint32_t h2u(float a, float b){
    __half2 h = __floats2half2_rn(a, b);
    return *reinterpret_cast<uint32_t*>(&h);
}
__device__ __forceinline__ uint4 pack8(const float4& p, const float4& q){
    uint4 u;
    u.x = h2u(p.x, p.y); u.y = h2u(p.z, p.w);
    u.z = h2u(q.x, q.y); u.w = h2u(q.z, q.w);
    return u;
}
__device__ __forceinline__ void mma16(float* c, const uint32_t* a, const uint32_t* b){
    asm volatile("mma.sync.aligned.m16n8k16.row.col.f32.f16.f16.f32 "
        "{%0,%1,%2,%3}, {%4,%5,%6,%7}, {%8,%9}, {%0,%1,%2,%3};"
        : "+f"(c[0]), "+f"(c[1]), "+f"(c[2]), "+f"(c[3])
        : "r"(a[0]), "r"(a[1]), "r"(a[2]), "r"(a[3]), "r"(b[0]), "r"(b[1]));
}
__device__ __forceinline__ void ldsm4(uint32_t* r, uint32_t addr){
    asm volatile("ldmatrix.sync.aligned.m8n8.x4.shared.b16 {%0,%1,%2,%3}, [%4];"
        : "=r"(r[0]), "=r"(r[1]), "=r"(r[2]), "=r"(r[3]) : "r"(addr));
}
__device__ __forceinline__ float gelu_e(float u){
    return 0.5f*u*(1.0f + erff(u*0.7071067811865476f));
}

// smem (K-chunk = 64 halfs = 128B/row):
//   stage: A 128 rows x 128B = 16K, B 64 rows x 128B = 8K  -> 24K; 2 stages = 48K
#define STG_BYTES 24576u
#define B_IN_STG  16384u
#define LB_OFF  49152u
#define LS_OFF  53248u
#define TW_OFF  53760u
#define SMEM_BYTES 54272

// ---------------- routing ----------------
__global__ void k_zero() { if (threadIdx.x < NEXP) g_cnt[threadIdx.x] = 0; }

__global__ void k_route(const int* __restrict__ ids) {
    int nk = blockIdx.x*blockDim.x + threadIdx.x;
    if (nk < NKTOT) {
        int e = ids[nk];
        int p = atomicAdd(&g_cnt[e], 1);
        g_list[e*NKTOT + p] = nk;
    }
}

// ---------------- LoRA t vectors ----------------
__global__ void k_t_up(const float* __restrict__ x, const int* __restrict__ ids,
                       const float* __restrict__ up_a) {
    int nk = blockIdx.x;
    int n  = nk / TOPK;
    int e  = ids[nk];
    int warp = threadIdx.x >> 5, lane = threadIdx.x & 31;
    const float4* xr = (const float4*)(x + (size_t)n*DIM);
    const float4* A  = (const float4*)(up_a + (size_t)e*RNK*DIM);
    #pragma unroll
    for (int rr = 0; rr < 4; rr++) {
        int r = warp*4 + rr;
        const float4* ar = A + (size_t)r*(DIM/4);
        float s = 0.f;
        for (int i = lane; i < DIM/4; i += 32) {
            float4 xv = xr[i], av = ar[i];
            s += xv.x*av.x + xv.y*av.y + xv.z*av.z + xv.w*av.w;
        }
        #pragma unroll
        for (int o = 16; o > 0; o >>= 1) s += __shfl_xor_sync(0xffffffffu, s, o);
        if (lane == 0) g_t[nk*RNK + r] = s;
    }
}

__global__ void k_t_down(const int* __restrict__ ids, const float* __restrict__ down_a) {
    int nk = blockIdx.x;
    int e  = ids[nk];
    int warp = threadIdx.x >> 5, lane = threadIdx.x & 31;
    const __half2* xr = (const __half2*)(g_act_h + (size_t)nk*HID);
    const float* A = down_a + (size_t)e*RNK*HID;
    #pragma unroll
    for (int rr = 0; rr < 4; rr++) {
        int r = warp*4 + rr;
        const float2* ar = (const float2*)(A + (size_t)r*HID);
        float s = 0.f;
        for (int i = lane; i < HID/2; i += 32) {
            float2 xv = __half22float2(xr[i]);
            float2 av = ar[i];
            s += xv.x*av.x + xv.y*av.y;
        }
        #pragma unroll
        for (int o = 16; o > 0; o >>= 1) s += __shfl_xor_sync(0xffffffffu, s, o);
        if (lane == 0) g_t2[nk*RNK + r] = s;
    }
}

// ---------------- up GEMM: fp16 HMMA, 128x64 tile, K-chunk 64, 1 barrier/chunk ----------------
__global__ __launch_bounds__(256, 2)
void k_up_tc(const float* __restrict__ x, const float* __restrict__ w_up,
             const float* __restrict__ up_b) {
    int e = blockIdx.z, cnt = g_cnt[e];
    int m0 = blockIdx.y * 128;
    if (m0 >= cnt) return;
    int j0p = blockIdx.x * 32;          // 32 output pairs (64 interleaved B rows)

    extern __shared__ __align__(16) char sm[];
    uint32_t sbase = smem_u32(sm);
    int tid = threadIdx.x, wid = tid >> 5, lid = tid & 31;

    int* ls = (int*)(sm + LS_OFF);
    if (tid < 128) {
        int m = m0 + tid;
        ls[tid] = g_list[e*NKTOT + ((m < cnt) ? m : 0)];
    }
    __syncthreads();

    // lb: 64 interleaved rows x 16 floats
    float* lb = (float*)(sm + LB_OFF);
    {
        const float* Bup = up_b + (size_t)e*(2*HID)*RNK;
        int row = tid >> 2, r4 = tid & 3;
        int grow = (row & 1) ? (HID + j0p + (row >> 1)) : (j0p + (row >> 1));
        ((float4*)lb)[tid] = ((const float4*)(Bup + (size_t)grow*RNK))[r4];
    }

    // producers: A: 2 thr/row, 32 floats (units as_*4..+3); B: 4 thr/row, 16 floats (units bs_*2,+1)
    int ar_ = tid >> 1, as_ = tid & 1;
    const float* arow = x + (size_t)(ls[ar_] >> 1)*DIM + as_*32;
    uint32_t aoff[4];
    #pragma unroll
    for (int q = 0; q < 4; q++)
        aoff[q] = (uint32_t)((ar_ << 7) + (((as_*4 + q) ^ (ar_ & 7)) << 4));
    int br_ = tid >> 2, bs_ = tid & 3;
    const float* W = w_up + (size_t)e*(2*HID)*(size_t)DIM;
    int bgrow = (br_ & 1) ? (HID + j0p + (br_ >> 1)) : (j0p + (br_ >> 1));
    const float* brow = W + (size_t)bgrow*DIM + bs_*16;
    uint32_t boff[2];
    #pragma unroll
    for (int q = 0; q < 2; q++)
        boff[q] = B_IN_STG + (uint32_t)((br_ << 7) + (((bs_*2 + q) ^ (br_ & 7)) << 4));

    // preload chunk 0 (packed)
    uint4 pa[4], pb[2];
    {
        const float4* asrc = (const float4*)arow;
        #pragma unroll
        for (int q = 0; q < 4; q++) pa[q] = pack8(asrc[2*q], asrc[2*q+1]);
        const float4* bsrc = (const float4*)brow;
        #pragma unroll
        for (int q = 0; q < 2; q++) pb[q] = pack8(bsrc[2*q], bsrc[2*q+1]);
    }
    #pragma unroll
    for (int q = 0; q < 4; q++) *(uint4*)(sm + aoff[q]) = pa[q];
    #pragma unroll
    for (int q = 0; q < 2; q++) *(uint4*)(sm + boff[q]) = pb[q];

    // consumer geometry: 4x2 warps, warp tile 32x32
    int warp_m = wid & 3, warp_n = wid >> 2;
    int lane7 = lid & 7, l3 = (lid >> 3) & 1, l4 = (lid >> 4) & 1;
    uint32_t offA[2], ua[4], offB[2], ub[4];
    #pragma unroll
    for (int mi = 0; mi < 2; mi++)
        offA[mi] = (uint32_t)((warp_m*32 + mi*16 + l3*8 + lane7) << 7);
    #pragma unroll
    for (int p = 0; p < 2; p++)
        offB[p] = B_IN_STG + (uint32_t)((warp_n*32 + p*16 + l4*8 + lane7) << 7);
    #pragma unroll
    for (int ks = 0; ks < 4; ks++) {
        ua[ks] = (uint32_t)((((2*ks + l4) ^ lane7) & 7) << 4);
        ub[ks] = (uint32_t)((((2*ks + l3) ^ lane7) & 7) << 4);
    }

    float acc[2][4][4];
    #pragma unroll
    for (int mi = 0; mi < 2; mi++)
        #pragma unroll
        for (int ni = 0; ni < 4; ni++)
            #pragma unroll
            for (int q = 0; q < 4; q++) acc[mi][ni][q] = 0.f;

    const int NC = DIM/64;
    for (int c = 0; c < NC; c++) {
        int s = c & 1;
        __syncthreads();                // stage s ready; s^1 free to overwrite
        if (c + 1 < NC) {
            const float4* asrc = (const float4*)(arow + (c+1)*64);
            #pragma unroll
            for (int q = 0; q < 4; q++) pa[q] = pack8(asrc[2*q], asrc[2*q+1]);
            const float4* bsrc = (const float4*)(brow + (c+1)*64);
            #pragma unroll
            for (int q = 0; q < 2; q++) pb[q] = pack8(bsrc[2*q], bsrc[2*q+1]);
        }
        uint32_t S = sbase + (uint32_t)s*STG_BYTES;
        #pragma unroll
        for (int ks = 0; ks < 4; ks++) {
            uint32_t bf[4][2];
            #pragma unroll
            for (int p = 0; p < 2; p++) {
                uint32_t t4[4];
                ldsm4(t4, S + offB[p] + ub[ks]);
                bf[2*p][0]   = t4[0]; bf[2*p][1]   = t4[1];
                bf[2*p+1][0] = t4[2]; bf[2*p+1][1] = t4[3];
            }
            #pragma unroll
            for (int mi = 0; mi < 2; mi++) {
                uint32_t af[4];
                ldsm4(af, S + offA[mi] + ua[ks]);
                #pragma unroll
                for (int ni = 0; ni < 4; ni++)
                    mma16(acc[mi][ni], af, bf[ni]);
            }
        }
        if (c + 1 < NC) {
            char* D = sm + (s^1)*STG_BYTES;
            #pragma unroll
            for (int q = 0; q < 4; q++) *(uint4*)(D + aoff[q]) = pa[q];
            #pragma unroll
            for (int q = 0; q < 2; q++) *(uint4*)(D + boff[q]) = pb[q];
        }
    }

    // direct epilogue: quad cols (2t,2t+1) = (u1,u2) of pair p
    int g = lid >> 2, t = lid & 3;
    #pragma unroll
    for (int mi = 0; mi < 2; mi++) {
        int r0 = warp_m*32 + mi*16 + g;
        int r1 = r0 + 8;
        float tr0[16], tr1[16];
        {
            const float4* t0p = (const float4*)(g_t + (size_t)ls[r0]*RNK);
            const float4* t1p = (const float4*)(g_t + (size_t)ls[r1]*RNK);
            #pragma unroll
            for (int q4 = 0; q4 < 4; q4++) {
                ((float4*)tr0)[q4] = t0p[q4];
                ((float4*)tr1)[q4] = t1p[q4];
            }
        }
        bool v0 = (m0 + r0 < cnt), v1 = (m0 + r1 < cnt);
        __half* o0 = g_act_h + (size_t)ls[r0]*HID + j0p;
        __half* o1 = g_act_h + (size_t)ls[r1]*HID + j0p;
        #pragma unroll
        for (int ni = 0; ni < 4; ni++) {
            int ccl = warp_n*32 + ni*8 + 2*t;   // interleaved row of u1 in lb
            int p   = ccl >> 1;                  // pair index [0,32)
            float l00 = 0.f, l01 = 0.f, l10 = 0.f, l11 = 0.f;
            #pragma unroll
            for (int r = 0; r < 16; r++) {
                float b0 = lb[ccl*16 + r], b1 = lb[(ccl+1)*16 + r];
                l00 += tr0[r]*b0; l01 += tr0[r]*b1;
                l10 += tr1[r]*b0; l11 += tr1[r]*b1;
            }
            float u1a = acc[mi][ni][0] + LSCALE*l00;
            float u2a = acc[mi][ni][1] + LSCALE*l01;
            float u1b = acc[mi][ni][2] + LSCALE*l10;
            float u2b = acc[mi][ni][3] + LSCALE*l11;
            if (v0) o0[p] = __float2half(gelu_e(u1a)*u2a);
            if (v1) o1[p] = __float2half(gelu_e(u1b)*u2b);
        }
    }
}

// ---------------- down GEMM: fp16 HMMA, 128x64 tile, K-chunk 64, 1 barrier/chunk ----------------
__global__ __launch_bounds__(256, 2)
void k_down_tc(const float* __restrict__ tw, const float* __restrict__ w_down,
               const float* __restrict__ down_b) {
    int e = blockIdx.z, cnt = g_cnt[e];
    int m0 = blockIdx.y * 128;
    if (m0 >= cnt) return;
    int d0 = blockIdx.x * 64;

    extern __shared__ __align__(16) char sm[];
    uint32_t sbase = smem_u32(sm);
    int tid = threadIdx.x, wid = tid >> 5, lid = tid & 31;

    int* ls = (int*)(sm + LS_OFF);
    float* twsm = (float*)(sm + TW_OFF);
    if (tid < 128) {
        int m = m0 + tid;
        int nk = g_list[e*NKTOT + ((m < cnt) ? m : 0)];
        ls[tid] = nk;
        twsm[tid] = tw[nk];
    }
    __syncthreads();

    float* lb = (float*)(sm + LB_OFF);
    {
        const float* Bdn = down_b + (size_t)e*DIM*RNK;
        int row = tid >> 2, r4 = tid & 3;
        ((float4*)lb)[tid] = ((const float4*)(Bdn + (size_t)(d0 + row)*RNK))[r4];
    }

    // producers: A (fp16 src): 2 thr/row, 64B each (units as_*4..+3); B: 4 thr/row, 16 floats
    int ar_ = tid >> 1, as_ = tid & 1;
    const uint4* arow = (const uint4*)(g_act_h + (size_t)ls[ar_]*HID) + as_*4;
    uint32_t aoff[4];
    #pragma unroll
    for (int q = 0; q < 4; q++)
        aoff[q] = (uint32_t)((ar_ << 7) + (((as_*4 + q) ^ (ar_ & 7)) << 4));
    int br_ = tid >> 2, bs_ = tid & 3;
    const float* W = w_down + (size_t)e*DIM*(size_t)HID;
    const float* brow = W + (size_t)(d0 + br_)*HID + bs_*16;
    uint32_t boff[2];
    #pragma unroll
    for (int q = 0; q < 2; q++)
        boff[q] = B_IN_STG + (uint32_t)((br_ << 7) + (((bs_*2 + q) ^ (br_ & 7)) << 4));

    uint4 pa[4], pb[2];
    {
        #pragma unroll
        for (int q = 0; q < 4; q++) pa[q] = arow[q];
        const float4* bsrc = (const float4*)brow;
        #pragma unroll
        for (int q = 0; q < 2; q++) pb[q] = pack8(bsrc[2*q], bsrc[2*q+1]);
    }
    #pragma unroll
    for (int q = 0; q < 4; q++) *(uint4*)(sm + aoff[q]) = pa[q];
    #pragma unroll
    for (int q = 0; q < 2; q++) *(uint4*)(sm + boff[q]) = pb[q];

    int warp_m = wid & 3, warp_n = wid >> 2;
    int lane7 = lid & 7, l3 = (lid >> 3) & 1, l4 = (lid >> 4) & 1;
    uint32_t offA[2], ua[4], offB[2], ub[4];
    #pragma unroll
    for (int mi = 0; mi < 2; mi++)
        offA[mi] = (uint32_t)((warp_m*32 + mi*16 + l3*8 + lane7) << 7);
    #pragma unroll
    for (int p = 0; p < 2; p++)
        offB[p] = B_IN_STG + (uint32_t)((warp_n*32 + p*16 + l4*8 + lane7) << 7);
    #pragma unroll
    for (int ks = 0; ks < 4; ks++) {
        ua[ks] = (uint32_t)((((2*ks + l4) ^ lane7) & 7) << 4);
        ub[ks] = (uint32_t)((((2*ks + l3) ^ lane7) & 7) << 4);
    }

    float acc[2][4][4];
    #pragma unroll
    for (int mi = 0; mi < 2; mi++)
        #pragma unroll
        for (int ni = 0; ni < 4; ni++)
            #pragma unroll
            for (int q = 0; q < 4; q++) acc[mi][ni][q] = 0.f;

    const int NC = HID/64;
    for (int c = 0; c < NC; c++) {
        int s = c & 1;
        __syncthreads();
        if (c + 1 < NC) {
            #pragma unroll
            for (int q = 0; q < 4; q++) pa[q] = arow[(c+1)*8 + q];
            const float4* bsrc = (const float4*)(brow + (c+1)*64);
            #pragma unroll
            for (int q = 0; q < 2; q++) pb[q] = pack8(bsrc[2*q], bsrc[2*q+1]);
        }
        uint32_t S = sbase + (uint32_t)s*STG_BYTES;
        #pragma unroll
        for (int ks = 0; ks < 4; ks++) {
            uint32_t bf[4][2];
            #pragma unroll
            for (int p = 0; p < 2; p++) {
                uint32_t t4[4];
                ldsm4(t4, S + offB[p] + ub[ks]);
                bf[2*p][0]   = t4[0]; bf[2*p][1]   = t4[1];
                bf[2*p+1][0] = t4[2]; bf[2*p+1][1] = t4[3];
            }
            #pragma unroll
            for (int mi = 0; mi < 2; mi++) {
                uint32_t af[4];
                ldsm4(af, S + offA[mi] + ua[ks]);
                #pragma unroll
                for (int ni = 0; ni < 4; ni++)
                    mma16(acc[mi][ni], af, bf[ni]);
            }
        }
        if (c + 1 < NC) {
            char* D = sm + (s^1)*STG_BYTES;
            #pragma unroll
            for (int q = 0; q < 4; q++) *(uint4*)(D + aoff[q]) = pa[q];
            #pragma unroll
            for (int q = 0; q < 2; q++) *(uint4*)(D + boff[q]) = pb[q];
        }
    }

    // direct epilogue: float2 stores
    int g = lid >> 2, t = lid & 3;
    #pragma unroll
    for (int mi = 0; mi < 2; mi++) {
        int r0 = warp_m*32 + mi*16 + g;
        int r1 = r0 + 8;
        float tr0[16], tr1[16];
        {
            const float4* t0p = (const float4*)(g_t2 + (size_t)ls[r0]*RNK);
            const float4* t1p = (const float4*)(g_t2 + (size_t)ls[r1]*RNK);
            #pragma unroll
            for (int q4 = 0; q4 < 4; q4++) {
                ((float4*)tr0)[q4] = t0p[q4];
                ((float4*)tr1)[q4] = t1p[q4];
            }
        }
        bool v0 = (m0 + r0 < cnt), v1 = (m0 + r1 < cnt);
        float tw0 = twsm[r0], tw1 = twsm[r1];
        float* o0 = g_down + (size_t)ls[r0]*DIM + d0;
        float* o1 = g_down + (size_t)ls[r1]*DIM + d0;
        #pragma unroll
        for (int ni = 0; ni < 4; ni++) {
            int cc = warp_n*32 + ni*8 + 2*t;
            float l00 = 0.f, l01 = 0.f, l10 = 0.f, l11 = 0.f;
            #pragma unroll
            for (int r = 0; r < 16; r++) {
                float b0 = lb[cc*16 + r], b1 = lb[(cc+1)*16 + r];
                l00 += tr0[r]*b0; l01 += tr0[r]*b1;
                l10 += tr1[r]*b0; l11 += tr1[r]*b1;
            }
            if (v0) *(float2*)(o0 + cc) = make_float2(
                (acc[mi][ni][0] + LSCALE*l00)*tw0, (acc[mi][ni][1] + LSCALE*l01)*tw0);
            if (v1) *(float2*)(o1 + cc) = make_float2(
                (acc[mi][ni][2] + LSCALE*l10)*tw1, (acc[mi][ni][3] + LSCALE*l11)*tw1);
        }
    }
}

// ---------------- deterministic k-sum ----------------
__global__ void k_combine(float* __restrict__ out) {
    int idx = blockIdx.x*blockDim.x + threadIdx.x;
    if (idx < N_TOK*DIM/4) {
        int n    = idx / (DIM/4);
        int rest = idx - n*(DIM/4);
        const float4* a = (const float4*)g_down + (size_t)(2*n)*(DIM/4) + rest;
        const float4* b = a + (DIM/4);
        float4 va = *a, vb = *b;
        ((float4*)out)[idx] = make_float4(va.x+vb.x, va.y+vb.y, va.z+vb.z, va.w+vb.w);
    }
}

// ---------------- launch ----------------
extern "C" void kernel_launch(void* const* d_in, const int* in_sizes, int n_in,
                              void* d_out, int out_size) {
    const float* x      = (const float*)d_in[0];
    const float* tw     = (const float*)d_in[1];
    const int*   ids    = (const int*)  d_in[2];
    const float* w_up   = (const float*)d_in[3];
    const float* w_down = (const float*)d_in[4];
    const float* up_a   = (const float*)d_in[5];
    const float* up_b   = (const float*)d_in[6];
    const float* down_a = (const float*)d_in[7];
    const float* down_b = (const float*)d_in[8];
    float* out = (float*)d_out;
    (void)in_sizes; (void)n_in; (void)out_size;

    cudaFuncSetAttribute(k_up_tc,   cudaFuncAttributeMaxDynamicSharedMemorySize, SMEM_BYTES);
    cudaFuncSetAttribute(k_down_tc, cudaFuncAttributeMaxDynamicSharedMemorySize, SMEM_BYTES);

    k_zero<<<1, 32>>>();
    k_route<<<(NKTOT+255)/256, 256>>>(ids);
    k_t_up<<<NKTOT, 128>>>(x, ids, up_a);
    k_up_tc<<<dim3(HID/32, NKTOT/128, NEXP), 256, SMEM_BYTES>>>(x, w_up, up_b);
    k_t_down<<<NKTOT, 128>>>(ids, down_a);
    k_down_tc<<<dim3(DIM/64, NKTOT/128, NEXP), 256, SMEM_BYTES>>>(tw, w_down, down_b);
    k_combine<<<(N_TOK*DIM/4 + 255)/256, 256>>>(out);
}

// round 12
// speedup vs baseline: 1.3249x; 1.3249x over previous
#include <cuda_runtime.h>
#include <cuda_fp16.h>
#include <math.h>
#include <cstdint>

#define N_TOK 1024
#define TOPK  2
#define NEXP  16
#define HID   1024
#define DIM   2048
#define RNK   16
#define NKTOT (N_TOK*TOPK)
#define LSCALE 0.25f

// ---------------- scratch (static device globals; no allocation) ----------------
__device__ int   g_cnt[NEXP];
__device__ int   g_list[NEXP*NKTOT];
__device__ __align__(16) float  g_t[NKTOT*RNK];
__device__ __align__(16) float  g_t2[NKTOT*RNK];
__device__ __align__(16) __half g_x_h[(size_t)N_TOK*DIM];
__device__ __align__(16) __half g_act_h[(size_t)NKTOT*HID];
__device__ __align__(16) float  g_down[(size_t)NKTOT*DIM];

// ---------------- helpers ----------------
__device__ __forceinline__ uint32_t smem_u32(const void* p){
    uint32_t a;
    asm("{ .reg .u64 t; cvta.to.shared.u64 t, %1; cvt.u32.u64 %0, t; }":"=r"(a):"l"(p));
    return a;
}
__device__ __forceinline__ uint32_t h2u(float a, float b){
    __half2 h = __floats2half2_rn(a, b);
    return *reinterpret_cast<uint32_t*>(&h);
}
__device__ __forceinline__ uint4 pack8(const float4& p, const float4& q){
    uint4 u;
    u.x = h2u(p.x, p.y); u.y = h2u(p.z, p.w);
    u.z = h2u(q.x, q.y); u.w = h2u(q.z, q.w);
    return u;
}
__device__ __forceinline__ void mma16(float* c, const uint32_t* a, const uint32_t* b){
    asm volatile("mma.sync.aligned.m16n8k16.row.col.f32.f16.f16.f32 "
        "{%0,%1,%2,%3}, {%4,%5,%6,%7}, {%8,%9}, {%0,%1,%2,%3};"
        : "+f"(c[0]), "+f"(c[1]), "+f"(c[2]), "+f"(c[3])
        : "r"(a[0]), "r"(a[1]), "r"(a[2]), "r"(a[3]), "r"(b[0]), "r"(b[1]));
}
__device__ __forceinline__ void ldsm4(uint32_t* r, uint32_t addr){
    asm volatile("ldmatrix.sync.aligned.m8n8.x4.shared.b16 {%0,%1,%2,%3}, [%4];"
        : "=r"(r[0]), "=r"(r[1]), "=r"(r[2]), "=r"(r[3]) : "r"(addr));
}
__device__ __forceinline__ float gelu_e(float u){
    return 0.5f*u*(1.0f + erff(u*0.7071067811865476f));
}

// cp.async helpers
#define CP16(dst, src) asm volatile("cp.async.ca.shared.global [%0], [%1], 16;" :: "r"(dst), "l"(src) : "memory")
#define CP_COMMIT()    asm volatile("cp.async.commit_group;" ::: "memory")
#define CP_WAIT0()     asm volatile("cp.async.wait_group 0;" ::: "memory")

// smem: 2 stages x (A 8K fp16 + B 4K fp16) = 24K, lb 4K, ls, tw
#define STG_BYTES 12288u
#define B_IN_STG  8192u
#define LB_OFF  24576u
#define LS_OFF  28672u
#define TW_OFF  29184u
#define SMEM_BYTES 29696

// pair-row fp16 layout: logical row r (32 halfs = 4 16B units), smem row j=r>>1 (128B),
// unit u in row r -> physical unit ((r&1)*4 | u) ^ (j&7)
__device__ __forceinline__ uint32_t hoff(int r, int u){
    int j = r >> 1;
    return (uint32_t)((j << 7) + (((((r & 1) << 2) | u) ^ (j & 7)) << 4));
}

// ---------------- routing ----------------
__global__ void k_zero() { if (threadIdx.x < NEXP) g_cnt[threadIdx.x] = 0; }

__global__ void k_route(const int* __restrict__ ids) {
    int nk = blockIdx.x*blockDim.x + threadIdx.x;
    if (nk < NKTOT) {
        int e = ids[nk];
        int p = atomicAdd(&g_cnt[e], 1);
        g_list[e*NKTOT + p] = nk;
    }
}

// ---------------- x -> fp16 (4MB, ~4us) ----------------
__global__ void k_x2h(const float* __restrict__ x) {
    int i = blockIdx.x*blockDim.x + threadIdx.x;   // 8 floats per thread
    const float4* s = (const float4*)x + i*2;
    float4 a = s[0], b = s[1];
    ((uint4*)g_x_h)[i] = pack8(a, b);
}

// ---------------- LoRA t vectors ----------------
__global__ void k_t_up(const float* __restrict__ x, const int* __restrict__ ids,
                       const float* __restrict__ up_a) {
    int nk = blockIdx.x;
    int n  = nk / TOPK;
    int e  = ids[nk];
    int warp = threadIdx.x >> 5, lane = threadIdx.x & 31;
    const float4* xr = (const float4*)(x + (size_t)n*DIM);
    const float4* A  = (const float4*)(up_a + (size_t)e*RNK*DIM);
    #pragma unroll
    for (int rr = 0; rr < 4; rr++) {
        int r = warp*4 + rr;
        const float4* ar = A + (size_t)r*(DIM/4);
        float s = 0.f;
        for (int i = lane; i < DIM/4; i += 32) {
            float4 xv = xr[i], av = ar[i];
            s += xv.x*av.x + xv.y*av.y + xv.z*av.z + xv.w*av.w;
        }
        #pragma unroll
        for (int o = 16; o > 0; o >>= 1) s += __shfl_xor_sync(0xffffffffu, s, o);
        if (lane == 0) g_t[nk*RNK + r] = s;
    }
}

__global__ void k_t_down(const int* __restrict__ ids, const float* __restrict__ down_a) {
    int nk = blockIdx.x;
    int e  = ids[nk];
    int warp = threadIdx.x >> 5, lane = threadIdx.x & 31;
    const __half2* xr = (const __half2*)(g_act_h + (size_t)nk*HID);
    const float* A = down_a + (size_t)e*RNK*HID;
    #pragma unroll
    for (int rr = 0; rr < 4; rr++) {
        int r = warp*4 + rr;
        const float2* ar = (const float2*)(A + (size_t)r*HID);
        float s = 0.f;
        for (int i = lane; i < HID/2; i += 32) {
            float2 xv = __half22float2(xr[i]);
            float2 av = ar[i];
            s += xv.x*av.x + xv.y*av.y;
        }
        #pragma unroll
        for (int o = 16; o > 0; o >>= 1) s += __shfl_xor_sync(0xffffffffu, s, o);
        if (lane == 0) g_t2[nk*RNK + r] = s;
    }
}

// ---------------- up GEMM: fp16 HMMA, 128x64 tile, A via cp.async, 1 barrier/chunk ----------------
__global__ __launch_bounds__(256, 2)
void k_up_tc(const float* __restrict__ w_up, const float* __restrict__ up_b) {
    int e = blockIdx.z, cnt = g_cnt[e];
    int m0 = blockIdx.y * 128;
    if (m0 >= cnt) return;
    int j0p = blockIdx.x * 32;          // 32 output pairs (64 interleaved rows)

    extern __shared__ __align__(16) char sm[];
    uint32_t sbase = smem_u32(sm);
    int tid = threadIdx.x, wid = tid >> 5, lid = tid & 31;

    int* ls = (int*)(sm + LS_OFF);
    if (tid < 128) {
        int m = m0 + tid;
        ls[tid] = g_list[e*NKTOT + ((m < cnt) ? m : 0)];
    }
    __syncthreads();

    // lb: 64 interleaved rows x 16 floats
    float* lb = (float*)(sm + LB_OFF);
    {
        const float* Bup = up_b + (size_t)e*(2*HID)*RNK;
        int row = tid >> 2, r4 = tid & 3;
        int grow = (row & 1) ? (HID + j0p + (row >> 1)) : (j0p + (row >> 1));
        ((float4*)lb)[tid] = ((const float4*)(Bup + (size_t)grow*RNK))[r4];
    }

    // producers:
    // A (fp16 gmem): 2 thr/row, 16 halfs each -> 2 x CP16 into units 2as_, 2as_+1
    int ar_ = tid >> 1, as_ = tid & 1;
    const __half* asrc = g_x_h + (size_t)(ls[ar_] >> 1)*DIM + as_*16;
    uint32_t aoff0 = hoff(ar_, 2*as_), aoff1 = hoff(ar_, 2*as_ + 1);
    // B (fp32 gmem): 4 thr/row, 8 floats -> pack8 -> 1 unit
    int br_ = tid >> 2, bs_ = tid & 3;
    const float* W = w_up + (size_t)e*(2*HID)*(size_t)DIM;
    int bgrow = (br_ & 1) ? (HID + j0p + (br_ >> 1)) : (j0p + (br_ >> 1));
    const float* brow = W + (size_t)bgrow*DIM + bs_*8;
    uint32_t boff = B_IN_STG + hoff(br_, bs_);

    // prologue: chunk 0 -> stage 0
    {
        CP16(sbase + aoff0, asrc);
        CP16(sbase + aoff1, asrc + 8);
        CP_COMMIT();
        const float4* bsrc = (const float4*)brow;
        *(uint4*)(sm + boff) = pack8(bsrc[0], bsrc[1]);
        CP_WAIT0();
    }
    __syncthreads();

    // consumer geometry: 4x2 warps, warp tile 32x32
    int warp_m = wid & 3, warp_n = wid >> 2;
    int lane7 = lid & 7, l3 = (lid >> 3) & 1, l4 = (lid >> 4) & 1;
    int rA = warp_m*32 + l3*8 + lane7;
    int jA = rA >> 1, rbA = (rA & 1) << 2, jmA = jA & 7;
    uint32_t offA[2] = { (uint32_t)(jA << 7), (uint32_t)((jA + 8) << 7) };
    uint32_t ua[2] = { (uint32_t)(((rbA | l4) ^ jmA) << 4),
                       (uint32_t)(((rbA | (2 + l4)) ^ jmA) << 4) };
    int rB = warp_n*32 + l4*8 + lane7;
    int jB = rB >> 1, rbB = (rB & 1) << 2, jmB = jB & 7;
    uint32_t offB[2] = { (uint32_t)((jB << 7) + B_IN_STG), (uint32_t)(((jB + 8) << 7) + B_IN_STG) };
    uint32_t ub[2] = { (uint32_t)(((rbB | l3) ^ jmB) << 4),
                       (uint32_t)(((rbB | (2 + l3)) ^ jmB) << 4) };

    float acc[2][4][4];
    #pragma unroll
    for (int mi = 0; mi < 2; mi++)
        #pragma unroll
        for (int ni = 0; ni < 4; ni++)
            #pragma unroll
            for (int q = 0; q < 4; q++) acc[mi][ni][q] = 0.f;

    const int NC = DIM/32;
    for (int c = 0; c < NC; c++) {
        int s = c & 1;
        uint32_t S = sbase + (uint32_t)s*STG_BYTES;
        uint32_t Dq = sbase + (uint32_t)(s^1)*STG_BYTES;
        float4 vb0, vb1;
        if (c + 1 < NC) {
            const __half* a2 = asrc + (c+1)*32;
            CP16(Dq + aoff0, a2);
            CP16(Dq + aoff1, a2 + 8);
            CP_COMMIT();
            const float4* bsrc = (const float4*)(brow + (c+1)*32);
            vb0 = bsrc[0]; vb1 = bsrc[1];
        }
        #pragma unroll
        for (int ks = 0; ks < 2; ks++) {
            uint32_t bf[4][2];
            #pragma unroll
            for (int p = 0; p < 2; p++) {
                uint32_t t4[4];
                ldsm4(t4, S + offB[p] + ub[ks]);
                bf[2*p][0]   = t4[0]; bf[2*p][1]   = t4[1];
                bf[2*p+1][0] = t4[2]; bf[2*p+1][1] = t4[3];
            }
            #pragma unroll
            for (int mi = 0; mi < 2; mi++) {
                uint32_t af[4];
                ldsm4(af, S + offA[mi] + ua[ks]);
                #pragma unroll
                for (int ni = 0; ni < 4; ni++)
                    mma16(acc[mi][ni], af, bf[ni]);
            }
        }
        if (c + 1 < NC) {
            *(uint4*)(sm + (s^1)*STG_BYTES + boff) = pack8(vb0, vb1);
            CP_WAIT0();
        }
        __syncthreads();
    }

    // direct epilogue: quad cols (2t,2t+1) = (u1,u2) of pair p
    int g = lid >> 2, t = lid & 3;
    #pragma unroll
    for (int mi = 0; mi < 2; mi++) {
        int r0 = warp_m*32 + mi*16 + g;
        int r1 = r0 + 8;
        float tr0[16], tr1[16];
        {
            const float4* t0p = (const float4*)(g_t + (size_t)ls[r0]*RNK);
            const float4* t1p = (const float4*)(g_t + (size_t)ls[r1]*RNK);
            #pragma unroll
            for (int q4 = 0; q4 < 4; q4++) {
                ((float4*)tr0)[q4] = t0p[q4];
                ((float4*)tr1)[q4] = t1p[q4];
            }
        }
        bool v0 = (m0 + r0 < cnt), v1 = (m0 + r1 < cnt);
        __half* o0 = g_act_h + (size_t)ls[r0]*HID + j0p;
        __half* o1 = g_act_h + (size_t)ls[r1]*HID + j0p;
        #pragma unroll
        for (int ni = 0; ni < 4; ni++) {
            int ccl = warp_n*32 + ni*8 + 2*t;
            int p   = ccl >> 1;
            float l00 = 0.f, l01 = 0.f, l10 = 0.f, l11 = 0.f;
            #pragma unroll
            for (int r = 0; r < 16; r++) {
                float b0 = lb[ccl*16 + r], b1 = lb[(ccl+1)*16 + r];
                l00 += tr0[r]*b0; l01 += tr0[r]*b1;
                l10 += tr1[r]*b0; l11 += tr1[r]*b1;
            }
            float u1a = acc[mi][ni][0] + LSCALE*l00;
            float u2a = acc[mi][ni][1] + LSCALE*l01;
            float u1b = acc[mi][ni][2] + LSCALE*l10;
            float u2b = acc[mi][ni][3] + LSCALE*l11;
            if (v0) o0[p] = __float2half(gelu_e(u1a)*u2a);
            if (v1) o1[p] = __float2half(gelu_e(u1b)*u2b);
        }
    }
}

// ---------------- down GEMM: fp16 HMMA, 128x64 tile, A via cp.async, 1 barrier/chunk ----------------
__global__ __launch_bounds__(256, 2)
void k_down_tc(const float* __restrict__ tw, const float* __restrict__ w_down,
               const float* __restrict__ down_b) {
    int e = blockIdx.z, cnt = g_cnt[e];
    int m0 = blockIdx.y * 128;
    if (m0 >= cnt) return;
    int d0 = blockIdx.x * 64;

    extern __shared__ __align__(16) char sm[];
    uint32_t sbase = smem_u32(sm);
    int tid = threadIdx.x, wid = tid >> 5, lid = tid & 31;

    int* ls = (int*)(sm + LS_OFF);
    float* twsm = (float*)(sm + TW_OFF);
    if (tid < 128) {
        int m = m0 + tid;
        int nk = g_list[e*NKTOT + ((m < cnt) ? m : 0)];
        ls[tid] = nk;
        twsm[tid] = tw[nk];
    }
    __syncthreads();

    float* lb = (float*)(sm + LB_OFF);
    {
        const float* Bdn = down_b + (size_t)e*DIM*RNK;
        int row = tid >> 2, r4 = tid & 3;
        ((float4*)lb)[tid] = ((const float4*)(Bdn + (size_t)(d0 + row)*RNK))[r4];
    }

    // producers: A fp16 gmem via cp.async; B fp32 pack
    int ar_ = tid >> 1, as_ = tid & 1;
    const __half* asrc = g_act_h + (size_t)ls[ar_]*HID + as_*16;
    uint32_t aoff0 = hoff(ar_, 2*as_), aoff1 = hoff(ar_, 2*as_ + 1);
    int br_ = tid >> 2, bs_ = tid & 3;
    const float* W = w_down + (size_t)e*DIM*(size_t)HID;
    const float* brow = W + (size_t)(d0 + br_)*HID + bs_*8;
    uint32_t boff = B_IN_STG + hoff(br_, bs_);

    {
        CP16(sbase + aoff0, asrc);
        CP16(sbase + aoff1, asrc + 8);
        CP_COMMIT();
        const float4* bsrc = (const float4*)brow;
        *(uint4*)(sm + boff) = pack8(bsrc[0], bsrc[1]);
        CP_WAIT0();
    }
    __syncthreads();

    int warp_m = wid & 3, warp_n = wid >> 2;
    int lane7 = lid & 7, l3 = (lid >> 3) & 1, l4 = (lid >> 4) & 1;
    int rA = warp_m*32 + l3*8 + lane7;
    int jA = rA >> 1, rbA = (rA & 1) << 2, jmA = jA & 7;
    uint32_t offA[2] = { (uint32_t)(jA << 7), (uint32_t)((jA + 8) << 7) };
    uint32_t ua[2] = { (uint32_t)(((rbA | l4) ^ jmA) << 4),
                       (uint32_t)(((rbA | (2 + l4)) ^ jmA) << 4) };
    int rB = warp_n*32 + l4*8 + lane7;
    int jB = rB >> 1, rbB = (rB & 1) << 2, jmB = jB & 7;
    uint32_t offB[2] = { (uint32_t)((jB << 7) + B_IN_STG), (uint32_t)(((jB + 8) << 7) + B_IN_STG) };
    uint32_t ub[2] = { (uint32_t)(((rbB | l3) ^ jmB) << 4),
                       (uint32_t)(((rbB | (2 + l3)) ^ jmB) << 4) };

    float acc[2][4][4];
    #pragma unroll
    for (int mi = 0; mi < 2; mi++)
        #pragma unroll
        for (int ni = 0; ni < 4; ni++)
            #pragma unroll
            for (int q = 0; q < 4; q++) acc[mi][ni][q] = 0.f;

    const int NC = HID/32;
    for (int c = 0; c < NC; c++) {
        int s = c & 1;
        uint32_t S = sbase + (uint32_t)s*STG_BYTES;
        uint32_t Dq = sbase + (uint32_t)(s^1)*STG_BYTES;
        float4 vb0, vb1;
        if (c + 1 < NC) {
            const __half* a2 = asrc + (c+1)*32;
            CP16(Dq + aoff0, a2);
            CP16(Dq + aoff1, a2 + 8);
            CP_COMMIT();
            const float4* bsrc = (const float4*)(brow + (c+1)*32);
            vb0 = bsrc[0]; vb1 = bsrc[1];
        }
        #pragma unroll
        for (int ks = 0; ks < 2; ks++) {
            uint32_t bf[4][2];
            #pragma unroll
            for (int p = 0; p < 2; p++) {
                uint32_t t4[4];
                ldsm4(t4, S + offB[p] + ub[ks]);
                bf[2*p][0]   = t4[0]; bf[2*p][1]   = t4[1];
                bf[2*p+1][0] = t4[2]; bf[2*p+1][1] = t4[3];
            }
            #pragma unroll
            for (int mi = 0; mi < 2; mi++) {
                uint32_t af[4];
                ldsm4(af, S + offA[mi] + ua[ks]);
                #pragma unroll
                for (int ni = 0; ni < 4; ni++)
                    mma16(acc[mi][ni], af, bf[ni]);
            }
        }
        if (c + 1 < NC) {
            *(uint4*)(sm + (s^1)*STG_BYTES + boff) = pack8(vb0, vb1);
            CP_WAIT0();
        }
        __syncthreads();
    }

    // direct epilogue: float2 stores
    int g = lid >> 2, t = lid & 3;
    #pragma unroll
    for (int mi = 0; mi < 2; mi++) {
        int r0 = warp_m*32 + mi*16 + g;
        int r1 = r0 + 8;
        float tr0[16], tr1[16];
        {
            const float4* t0p = (const float4*)(g_t2 + (size_t)ls[r0]*RNK);
            const float4* t1p = (const float4*)(g_t2 + (size_t)ls[r1]*RNK);
            #pragma unroll
            for (int q4 = 0; q4 < 4; q4++) {
                ((float4*)tr0)[q4] = t0p[q4];
                ((float4*)tr1)[q4] = t1p[q4];
            }
        }
        bool v0 = (m0 + r0 < cnt), v1 = (m0 + r1 < cnt);
        float tw0 = twsm[r0], tw1 = twsm[r1];
        float* o0 = g_down + (size_t)ls[r0]*DIM + d0;
        float* o1 = g_down + (size_t)ls[r1]*DIM + d0;
        #pragma unroll
        for (int ni = 0; ni < 4; ni++) {
            int cc = warp_n*32 + ni*8 + 2*t;
            float l00 = 0.f, l01 = 0.f, l10 = 0.f, l11 = 0.f;
            #pragma unroll
            for (int r = 0; r < 16; r++) {
                float b0 = lb[cc*16 + r], b1 = lb[(cc+1)*16 + r];
                l00 += tr0[r]*b0; l01 += tr0[r]*b1;
                l10 += tr1[r]*b0; l11 += tr1[r]*b1;
            }
            if (v0) *(float2*)(o0 + cc) = make_float2(
                (acc[mi][ni][0] + LSCALE*l00)*tw0, (acc[mi][ni][1] + LSCALE*l01)*tw0);
            if (v1) *(float2*)(o1 + cc) = make_float2(
                (acc[mi][ni][2] + LSCALE*l10)*tw1, (acc[mi][ni][3] + LSCALE*l11)*tw1);
        }
    }
}

// ---------------- deterministic k-sum ----------------
__global__ void k_combine(float* __restrict__ out) {
    int idx = blockIdx.x*blockDim.x + threadIdx.x;
    if (idx < N_TOK*DIM/4) {
        int n    = idx / (DIM/4);
        int rest = idx - n*(DIM/4);
        const float4* a = (const float4*)g_down + (size_t)(2*n)*(DIM/4) + rest;
        const float4* b = a + (DIM/4);
        float4 va = *a, vb = *b;
        ((float4*)out)[idx] = make_float4(va.x+vb.x, va.y+vb.y, va.z+vb.z, va.w+vb.w);
    }
}

// ---------------- launch ----------------
extern "C" void kernel_launch(void* const* d_in, const int* in_sizes, int n_in,
                              void* d_out, int out_size) {
    const float* x      = (const float*)d_in[0];
    const float* tw     = (const float*)d_in[1];
    const int*   ids    = (const int*)  d_in[2];
    const float* w_up   = (const float*)d_in[3];
    const float* w_down = (const float*)d_in[4];
    const float* up_a   = (const float*)d_in[5];
    const float* up_b   = (const float*)d_in[6];
    const float* down_a = (const float*)d_in[7];
    const float* down_b = (const float*)d_in[8];
    float* out = (float*)d_out;
    (void)in_sizes; (void)n_in; (void)out_size;

    cudaFuncSetAttribute(k_up_tc,   cudaFuncAttributeMaxDynamicSharedMemorySize, SMEM_BYTES);
    cudaFuncSetAttribute(k_down_tc, cudaFuncAttributeMaxDynamicSharedMemorySize, SMEM_BYTES);

    k_zero<<<1, 32>>>();
    k_route<<<(NKTOT+255)/256, 256>>>(ids);
    k_x2h<<<(N_TOK*DIM/8)/256, 256>>>(x);
    k_t_up<<<NKTOT, 128>>>(x, ids, up_a);
    k_up_tc<<<dim3(HID/32, NKTOT/128, NEXP), 256, SMEM_BYTES>>>(w_up, up_b);
    k_t_down<<<NKTOT, 128>>>(ids, down_a);
    k_down_tc<<<dim3(DIM/64, NKTOT/128, NEXP), 256, SMEM_BYTES>>>(tw, w_down, down_b);
    k_combine<<<(N_TOK*DIM/4 + 255)/256, 256>>>(out);
}